// round 1
// baseline (speedup 1.0000x reference)
#include <cuda_runtime.h>

// Problem constants (fixed by the reference)
#define BB 512
#define TT 256
#define CC 128
#define HH 128
#define BTH (BB * TT * HH)   // 16,777,216

// Scratch for q projection (allocation-free rule: __device__ global)
__device__ float g_q[(size_t)BTH];

// ---------------------------------------------------------------------------
// Kernel 1: projection GEMM.  out = x @ W   for W in {Wk, Wq, Wv}
// M = B*T = 131072, N = 128, K = 128.
// Block: 256 threads, computes a 128x128 output tile (one W selected by blockIdx.y).
// smem: x tile 128x128 (64KB) + W 128x128 (64KB) = 128KB.
// Each thread: 8x8 register microtile.
// ---------------------------------------------------------------------------
__global__ void __launch_bounds__(256, 1)
proj_kernel(const float* __restrict__ x,
            const float* __restrict__ Wk,
            const float* __restrict__ Wq,
            const float* __restrict__ Wv,
            float* __restrict__ k_out,
            float* __restrict__ v_out)
{
    extern __shared__ float sm[];
    float* xs = sm;                 // [128][128]
    float* ws = sm + 128 * 128;     // [128][128]

    const int tid   = threadIdx.x;
    const int tile  = blockIdx.x;   // row tile (0..1023)
    const int which = blockIdx.y;   // 0=k, 1=q, 2=v

    const float* W   = (which == 0) ? Wk : (which == 1) ? Wq : Wv;
    float*       out = (which == 0) ? k_out : (which == 1) ? g_q : v_out;

    // Cooperative loads (both tiles are 4096 float4s, contiguous)
    const float4* xg  = (const float4*)(x + (size_t)tile * 128 * CC);
    const float4* wg  = (const float4*)W;
    float4* xs4 = (float4*)xs;
    float4* ws4 = (float4*)ws;
#pragma unroll
    for (int i = 0; i < 16; i++) {
        xs4[tid + i * 256] = xg[tid + i * 256];
        ws4[tid + i * 256] = wg[tid + i * 256];
    }
    __syncthreads();

    const int ty = tid >> 4;        // 0..15
    const int tx = tid & 15;        // 0..15
    const int r0 = ty * 8;
    const int c0 = tx * 8;

    float acc[8][8];
#pragma unroll
    for (int i = 0; i < 8; i++)
#pragma unroll
        for (int j = 0; j < 8; j++) acc[i][j] = 0.0f;

#pragma unroll 4
    for (int kk = 0; kk < 128; kk++) {
        float a[8];
#pragma unroll
        for (int i = 0; i < 8; i++) a[i] = xs[(r0 + i) * 128 + kk];
        float4 b0 = *(const float4*)&ws[kk * 128 + c0];
        float4 b1 = *(const float4*)&ws[kk * 128 + c0 + 4];
        float bb[8] = {b0.x, b0.y, b0.z, b0.w, b1.x, b1.y, b1.z, b1.w};
#pragma unroll
        for (int i = 0; i < 8; i++)
#pragma unroll
            for (int j = 0; j < 8; j++) acc[i][j] = fmaf(a[i], bb[j], acc[i][j]);
    }

    // Write out 8 rows x 8 cols per thread (vectorized)
#pragma unroll
    for (int i = 0; i < 8; i++) {
        float* orow = out + ((size_t)tile * 128 + r0 + i) * HH + c0;
        float4 o0 = {acc[i][0], acc[i][1], acc[i][2], acc[i][3]};
        float4 o1 = {acc[i][4], acc[i][5], acc[i][6], acc[i][7]};
        *(float4*)orow       = o0;
        *(float4*)(orow + 4) = o1;
    }
}

// ---------------------------------------------------------------------------
// Kernel 2: causal flash attention.
// Grid: (4 q-tiles, 512 batches). Block: 256 threads = one 64-row Q tile.
// smem: Q, K, V tiles 64x128 padded to 132 cols (33KB each) + P 64x64 (16KB).
// Thread (ty,tx): S microtile rows ty*4..+3, key-cols tx+16j (j=0..3);
//                 O accumulator rows ty*4..+3, head-cols tx*8..+7.
// Each Q row is owned by 16 consecutive lanes of one warp -> in-warp softmax.
// ---------------------------------------------------------------------------
#define LDK 132
#define NEG_BIG (-1.0e30f)

__global__ void __launch_bounds__(256, 1)
attn_kernel(const float* __restrict__ kglob,
            const float* __restrict__ vglob,
            float* __restrict__ outg)
{
    extern __shared__ float sm[];
    float* Qs = sm;                       // [64][LDK]
    float* Ks = Qs + 64 * LDK;
    float* Vs = Ks + 64 * LDK;
    float* Ps = Vs + 64 * LDK;            // [64][64]

    const int tid = threadIdx.x;
    const int qt  = blockIdx.x;           // 0..3
    const int b   = blockIdx.y;           // 0..511
    const float scale = 0.08838834764831845f;  // C^-0.5

    // Load Q tile (64 rows x 128 cols = 2048 float4)
    {
        const float4* qsrc = (const float4*)(g_q + ((size_t)b * TT + qt * 64) * HH);
#pragma unroll
        for (int i = tid; i < 2048; i += 256) {
            int row = i >> 5, c4 = i & 31;
            *(float4*)&Qs[row * LDK + c4 * 4] = qsrc[i];
        }
    }

    const int ty = tid >> 4;   // 0..15 (row group)
    const int tx = tid & 15;   // 0..15

    float m[4], l[4], acc[4][8];
#pragma unroll
    for (int i = 0; i < 4; i++) {
        m[i] = NEG_BIG;
        l[i] = 0.0f;
#pragma unroll
        for (int j = 0; j < 8; j++) acc[i][j] = 0.0f;
    }

    for (int st = 0; st <= qt; st++) {
        __syncthreads();   // protect Ks/Vs from previous iteration readers

        // Load K and V tiles for this key block
        {
            const float4* ksrc = (const float4*)(kglob + ((size_t)b * TT + st * 64) * HH);
            const float4* vsrc = (const float4*)(vglob + ((size_t)b * TT + st * 64) * HH);
#pragma unroll
            for (int i = tid; i < 2048; i += 256) {
                int row = i >> 5, c4 = i & 31;
                *(float4*)&Ks[row * LDK + c4 * 4] = ksrc[i];
                *(float4*)&Vs[row * LDK + c4 * 4] = vsrc[i];
            }
        }
        __syncthreads();

        // --- S = Q @ K^T microtile (4 rows x 4 key-cols), vectorized over k ---
        float s[4][4];
#pragma unroll
        for (int i = 0; i < 4; i++)
#pragma unroll
            for (int j = 0; j < 4; j++) s[i][j] = 0.0f;

#pragma unroll 2
        for (int kk = 0; kk < 128; kk += 4) {
            float4 a4[4], b4[4];
#pragma unroll
            for (int i = 0; i < 4; i++)
                a4[i] = *(const float4*)&Qs[(ty * 4 + i) * LDK + kk];
#pragma unroll
            for (int j = 0; j < 4; j++)
                b4[j] = *(const float4*)&Ks[(tx + 16 * j) * LDK + kk];
#pragma unroll
            for (int i = 0; i < 4; i++)
#pragma unroll
                for (int j = 0; j < 4; j++) {
                    s[i][j] = fmaf(a4[i].x, b4[j].x, s[i][j]);
                    s[i][j] = fmaf(a4[i].y, b4[j].y, s[i][j]);
                    s[i][j] = fmaf(a4[i].z, b4[j].z, s[i][j]);
                    s[i][j] = fmaf(a4[i].w, b4[j].w, s[i][j]);
                }
        }

        // Scale + causal mask (only the diagonal tile needs masking)
#pragma unroll
        for (int i = 0; i < 4; i++)
#pragma unroll
            for (int j = 0; j < 4; j++) {
                s[i][j] *= scale;
                if (st == qt) {
                    int key  = tx + 16 * j;
                    int qrow = ty * 4 + i;
                    if (key > qrow) s[i][j] = NEG_BIG;
                }
            }

        // --- Online softmax, per row (16 lanes per row, in-warp) ---
#pragma unroll
        for (int i = 0; i < 4; i++) {
            float mt = s[i][0];
            mt = fmaxf(mt, s[i][1]);
            mt = fmaxf(mt, s[i][2]);
            mt = fmaxf(mt, s[i][3]);
#pragma unroll
            for (int o = 1; o < 16; o <<= 1)
                mt = fmaxf(mt, __shfl_xor_sync(0xffffffffu, mt, o));
            float mnew  = fmaxf(m[i], mt);
            float alpha = expf(m[i] - mnew);
            float psum  = 0.0f;
#pragma unroll
            for (int j = 0; j < 4; j++) {
                float p = expf(s[i][j] - mnew);
                Ps[(ty * 4 + i) * 64 + tx + 16 * j] = p;
                psum += p;
            }
#pragma unroll
            for (int o = 1; o < 16; o <<= 1)
                psum += __shfl_xor_sync(0xffffffffu, psum, o);
            l[i] = l[i] * alpha + psum;
            m[i] = mnew;
#pragma unroll
            for (int j = 0; j < 8; j++) acc[i][j] *= alpha;
        }
        __syncwarp();   // Ps produced/consumed within one warp

        // --- O += P @ V  (rows ty*4..+3, head cols tx*8..+7) ---
#pragma unroll 4
        for (int ss = 0; ss < 64; ss++) {
            float p0 = Ps[(ty * 4 + 0) * 64 + ss];
            float p1 = Ps[(ty * 4 + 1) * 64 + ss];
            float p2 = Ps[(ty * 4 + 2) * 64 + ss];
            float p3 = Ps[(ty * 4 + 3) * 64 + ss];
            float4 v0 = *(const float4*)&Vs[ss * LDK + tx * 8];
            float4 v1 = *(const float4*)&Vs[ss * LDK + tx * 8 + 4];
            float vv[8] = {v0.x, v0.y, v0.z, v0.w, v1.x, v1.y, v1.z, v1.w};
#pragma unroll
            for (int j = 0; j < 8; j++) {
                acc[0][j] = fmaf(p0, vv[j], acc[0][j]);
                acc[1][j] = fmaf(p1, vv[j], acc[1][j]);
                acc[2][j] = fmaf(p2, vv[j], acc[2][j]);
                acc[3][j] = fmaf(p3, vv[j], acc[3][j]);
            }
        }
    }

    // Final normalize + write out
#pragma unroll
    for (int i = 0; i < 4; i++) {
        float inv = 1.0f / l[i];
        float* orow = outg + ((size_t)b * TT + qt * 64 + ty * 4 + i) * HH + tx * 8;
        float4 o0 = {acc[i][0] * inv, acc[i][1] * inv, acc[i][2] * inv, acc[i][3] * inv};
        float4 o1 = {acc[i][4] * inv, acc[i][5] * inv, acc[i][6] * inv, acc[i][7] * inv};
        *(float4*)orow       = o0;
        *(float4*)(orow + 4) = o1;
    }
}

// ---------------------------------------------------------------------------
// Launch: projections (k,v -> d_out regions, q -> scratch), then attention.
// Output layout assumption: (out, k, v) flattened in return order.
// ---------------------------------------------------------------------------
extern "C" void kernel_launch(void* const* d_in, const int* in_sizes, int n_in,
                              void* d_out, int out_size)
{
    const float* x  = (const float*)d_in[0];
    const float* Wk = (const float*)d_in[1];
    const float* Wq = (const float*)d_in[2];
    const float* Wv = (const float*)d_in[3];

    float* out  = (float*)d_out;
    float* kout = out + (size_t)BTH;
    float* vout = out + 2 * (size_t)BTH;

    const int proj_smem = 2 * 128 * 128 * (int)sizeof(float);                 // 131072
    const int attn_smem = (3 * 64 * LDK + 64 * 64) * (int)sizeof(float);      // 117760

    cudaFuncSetAttribute(proj_kernel, cudaFuncAttributeMaxDynamicSharedMemorySize, proj_smem);
    cudaFuncSetAttribute(attn_kernel, cudaFuncAttributeMaxDynamicSharedMemorySize, attn_smem);

    proj_kernel<<<dim3(1024, 3), 256, proj_smem>>>(x, Wk, Wq, Wv, kout, vout);
    attn_kernel<<<dim3(4, 512), 256, attn_smem>>>(kout, vout, out);
}

// round 3
// speedup vs baseline: 2.8171x; 2.8171x over previous
#include <cuda_runtime.h>
#include <cstdint>

#define BB 512
#define TT 256
#define CC 128
#define HH 128
#define BTH (BB * TT * HH)   // 16,777,216

// Scratch for q projection (allocation-free rule: __device__ global)
__device__ float g_q[(size_t)BTH];

// fp32 -> tf32 with round-to-nearest (unbiased)
__device__ __forceinline__ uint32_t f2tf32(float f) {
    uint32_t r;
    asm("cvt.rna.tf32.f32 %0, %1;" : "=r"(r) : "f"(f));
    return r;
}

// m16n8k8 tf32 MMA, D == C accumulate in-place
__device__ __forceinline__ void mma_tf32(float acc[4], const uint32_t a[4],
                                         uint32_t b0, uint32_t b1) {
    asm volatile(
        "mma.sync.aligned.m16n8k8.row.col.f32.tf32.tf32.f32 "
        "{%0,%1,%2,%3}, {%4,%5,%6,%7}, {%8,%9}, {%0,%1,%2,%3};"
        : "+f"(acc[0]), "+f"(acc[1]), "+f"(acc[2]), "+f"(acc[3])
        : "r"(a[0]), "r"(a[1]), "r"(a[2]), "r"(a[3]), "r"(b0), "r"(b1));
}

// ===========================================================================
// Kernel 1: projection via mma.sync tf32.  {k,q,v} = x @ {Wk,Wq,Wv}
// CTA: 128x128x128 tile. 8 warps = 4 m-groups x 2 n-groups.
// smem: xs [128][132] (A, row-major, conflict-free frags),
//       ws [128][136] (B = W K-major [k][n], conflict-free frags).
// ===========================================================================
#define LDA 132
#define LDB 136
#define PROJ_SMEM ((128 * LDA + 128 * LDB) * 4)

__device__ __forceinline__ void load_w_smem(const float* __restrict__ W,
                                            uint32_t* __restrict__ ws, int tid) {
    const float4* wg = (const float4*)W;
#pragma unroll
    for (int j = 0; j < 16; j++) {
        int i4 = tid + j * 256;
        float4 v = wg[i4];
        int row = i4 >> 5;
        int c4  = (i4 & 31) * 4;
        uint4 t = {f2tf32(v.x), f2tf32(v.y), f2tf32(v.z), f2tf32(v.w)};
        *(uint4*)&ws[row * LDB + c4] = t;
    }
}

__device__ __forceinline__ void do_proj(const uint32_t* __restrict__ xs,
                                        const uint32_t* __restrict__ ws,
                                        float* __restrict__ outp,
                                        int mbase, int nbase, int g, int c) {
    float acc[2][8][4];
#pragma unroll
    for (int mt = 0; mt < 2; mt++)
#pragma unroll
        for (int nt = 0; nt < 8; nt++)
#pragma unroll
            for (int e = 0; e < 4; e++) acc[mt][nt][e] = 0.0f;

#pragma unroll
    for (int k = 0; k < 16; k++) {
        uint32_t a[2][4];
#pragma unroll
        for (int mt = 0; mt < 2; mt++) {
            const uint32_t* xr = xs + (mbase + mt * 16 + g) * LDA + k * 8 + c;
            a[mt][0] = xr[0];
            a[mt][2] = xr[4];
            a[mt][1] = xr[8 * LDA];
            a[mt][3] = xr[8 * LDA + 4];
        }
#pragma unroll
        for (int nt = 0; nt < 8; nt++) {
            const uint32_t* wr = ws + (k * 8 + c) * LDB + nbase + nt * 8 + g;
            uint32_t b0 = wr[0];
            uint32_t b1 = wr[4 * LDB];
            mma_tf32(acc[0][nt], a[0], b0, b1);
            mma_tf32(acc[1][nt], a[1], b0, b1);
        }
    }

    // Epilogue: c0/c1 at (row, 2c), c2/c3 at (row+8, 2c)
#pragma unroll
    for (int mt = 0; mt < 2; mt++) {
        int row = mbase + mt * 16 + g;
#pragma unroll
        for (int nt = 0; nt < 8; nt++) {
            int col = nbase + nt * 8 + 2 * c;
            float2 lo = {acc[mt][nt][0], acc[mt][nt][1]};
            float2 hi = {acc[mt][nt][2], acc[mt][nt][3]};
            *(float2*)(outp + (size_t)row * HH + col)       = lo;
            *(float2*)(outp + (size_t)(row + 8) * HH + col) = hi;
        }
    }
}

__global__ void __launch_bounds__(256, 1)
proj_mma(const float* __restrict__ x,
         const float* __restrict__ Wk,
         const float* __restrict__ Wq,
         const float* __restrict__ Wv,
         float* __restrict__ kout,
         float* __restrict__ vout)
{
    extern __shared__ uint32_t sm[];
    uint32_t* xs = sm;
    uint32_t* ws = sm + 128 * LDA;

    const int tid  = threadIdx.x;
    const int tile = blockIdx.x;
    const int w    = tid >> 5;
    const int lane = tid & 31;
    const int g    = lane >> 2;
    const int c    = lane & 3;
    const int mbase = (w >> 1) * 32;
    const int nbase = (w & 1) * 64;

    // Load x tile -> xs (tf32)
    {
        const float4* xg = (const float4*)(x + (size_t)tile * 128 * CC);
#pragma unroll
        for (int j = 0; j < 16; j++) {
            int i4 = tid + j * 256;
            float4 v = xg[i4];
            int row = i4 >> 5;
            int c4  = (i4 & 31) * 4;
            uint4 t = {f2tf32(v.x), f2tf32(v.y), f2tf32(v.z), f2tf32(v.w)};
            *(uint4*)&xs[row * LDA + c4] = t;
        }
    }

    // Phase K
    load_w_smem(Wk, ws, tid);
    __syncthreads();
    do_proj(xs, ws, kout + (size_t)tile * 128 * HH, mbase, nbase, g, c);

    // Phase Q
    __syncthreads();
    load_w_smem(Wq, ws, tid);
    __syncthreads();
    do_proj(xs, ws, g_q + (size_t)tile * 128 * HH, mbase, nbase, g, c);

    // Phase V
    __syncthreads();
    load_w_smem(Wv, ws, tid);
    __syncthreads();
    do_proj(xs, ws, vout + (size_t)tile * 128 * HH, mbase, nbase, g, c);
}

// ===========================================================================
// Kernel 2: causal flash attention via mma.sync tf32.
// Grid (2 q-tiles, 512 batches), 256 threads. Warp w owns q-rows w*16..+15.
// Key tiles of 64. S: 8 n-tiles; PV: 16 n-tiles; P staged via smem (tf32).
// smem: Qs[128][132], Ks[64][132], Vs[64][136], Ps[128][68]  (~171KB)
// ===========================================================================
#define LDP 68
#define ATTN_SMEM ((128 * LDA + 64 * LDA + 64 * LDB + 128 * LDP) * 4)
#define NEG_BIG (-1.0e30f)

__global__ void __launch_bounds__(256, 1)
attn_mma(const float* __restrict__ kg,
         const float* __restrict__ vg,
         float* __restrict__ outg)
{
    extern __shared__ uint32_t sm[];
    uint32_t* Qs = sm;                    // [128][132]
    uint32_t* Ks = Qs + 128 * LDA;        // [64][132]
    uint32_t* Vs = Ks + 64 * LDA;         // [64][136]
    uint32_t* Ps = Vs + 64 * LDB;         // [128][68] (tf32 bits)

    const int tid  = threadIdx.x;
    const int qt   = blockIdx.x;          // 0..1 (128 q-rows each)
    const int b    = blockIdx.y;          // 0..511
    const int w    = tid >> 5;
    const int lane = tid & 31;
    const int g    = lane >> 2;
    const int c    = lane & 3;
    const int rb   = w * 16;              // warp's q-row base within tile
    const float scale = 0.08838834764831845f;  // C^-0.5

    // Load Q tile (tf32)
    {
        const float4* qg4 = (const float4*)(g_q + ((size_t)b * TT + qt * 128) * HH);
#pragma unroll
        for (int j = 0; j < 16; j++) {
            int i4 = tid + j * 256;
            float4 v = qg4[i4];
            int row = i4 >> 5;
            int c4  = (i4 & 31) * 4;
            uint4 t = {f2tf32(v.x), f2tf32(v.y), f2tf32(v.z), f2tf32(v.w)};
            *(uint4*)&Qs[row * LDA + c4] = t;
        }
    }

    float m0 = NEG_BIG, m1 = NEG_BIG, l0 = 0.0f, l1 = 0.0f;
    float o[16][4];
#pragma unroll
    for (int nt = 0; nt < 16; nt++)
#pragma unroll
        for (int e = 0; e < 4; e++) o[nt][e] = 0.0f;

    const int row0 = qt * 128 + rb + g;   // global q row (first of pair)
    const int row1 = row0 + 8;
    const int nkt  = qt ? 4 : 2;

    for (int st = 0; st < nkt; st++) {
        __syncthreads();   // prior iteration finished reading Ks/Vs
        {
            const float4* k4 = (const float4*)(kg + ((size_t)b * TT + st * 64) * HH);
            const float4* v4 = (const float4*)(vg + ((size_t)b * TT + st * 64) * HH);
#pragma unroll
            for (int j = 0; j < 8; j++) {
                int i4 = tid + j * 256;
                float4 kv = k4[i4];
                float4 vv = v4[i4];
                int row = i4 >> 5;
                int c4  = (i4 & 31) * 4;
                uint4 tk = {f2tf32(kv.x), f2tf32(kv.y), f2tf32(kv.z), f2tf32(kv.w)};
                uint4 tv = {f2tf32(vv.x), f2tf32(vv.y), f2tf32(vv.z), f2tf32(vv.w)};
                *(uint4*)&Ks[row * LDA + c4] = tk;
                *(uint4*)&Vs[row * LDB + c4] = tv;
            }
        }
        __syncthreads();

        // ---- S = Q K^T : 8 n-tiles of keys, 16 k-steps over head dim ----
        float s[8][4];
#pragma unroll
        for (int nt = 0; nt < 8; nt++)
#pragma unroll
            for (int e = 0; e < 4; e++) s[nt][e] = 0.0f;

#pragma unroll
        for (int k = 0; k < 16; k++) {
            uint32_t a[4];
            const uint32_t* qr = Qs + (rb + g) * LDA + k * 8 + c;
            a[0] = qr[0];
            a[2] = qr[4];
            a[1] = qr[8 * LDA];
            a[3] = qr[8 * LDA + 4];
#pragma unroll
            for (int nt = 0; nt < 8; nt++) {
                // B[k'][n] = K[n][k']  (K row-major [key][head])
                const uint32_t* kr = Ks + (nt * 8 + g) * LDA + k * 8 + c;
                mma_tf32(s[nt], a, kr[0], kr[4]);
            }
        }

        // ---- scale + causal mask + online softmax ----
        float mx0 = NEG_BIG, mx1 = NEG_BIG;
#pragma unroll
        for (int nt = 0; nt < 8; nt++) {
            int k0 = st * 64 + nt * 8 + 2 * c;
            s[nt][0] = (k0     <= row0) ? s[nt][0] * scale : NEG_BIG;
            s[nt][1] = (k0 + 1 <= row0) ? s[nt][1] * scale : NEG_BIG;
            s[nt][2] = (k0     <= row1) ? s[nt][2] * scale : NEG_BIG;
            s[nt][3] = (k0 + 1 <= row1) ? s[nt][3] * scale : NEG_BIG;
            mx0 = fmaxf(mx0, fmaxf(s[nt][0], s[nt][1]));
            mx1 = fmaxf(mx1, fmaxf(s[nt][2], s[nt][3]));
        }
#pragma unroll
        for (int off = 1; off < 4; off <<= 1) {
            mx0 = fmaxf(mx0, __shfl_xor_sync(0xffffffffu, mx0, off));
            mx1 = fmaxf(mx1, __shfl_xor_sync(0xffffffffu, mx1, off));
        }
        float mn0 = fmaxf(m0, mx0);
        float mn1 = fmaxf(m1, mx1);
        float al0 = __expf(m0 - mn0);
        float al1 = __expf(m1 - mn1);
        float ps0 = 0.0f, ps1 = 0.0f;
#pragma unroll
        for (int nt = 0; nt < 8; nt++) {
            s[nt][0] = __expf(s[nt][0] - mn0);
            s[nt][1] = __expf(s[nt][1] - mn0);
            s[nt][2] = __expf(s[nt][2] - mn1);
            s[nt][3] = __expf(s[nt][3] - mn1);
            ps0 += s[nt][0] + s[nt][1];
            ps1 += s[nt][2] + s[nt][3];
        }
#pragma unroll
        for (int off = 1; off < 4; off <<= 1) {
            ps0 += __shfl_xor_sync(0xffffffffu, ps0, off);
            ps1 += __shfl_xor_sync(0xffffffffu, ps1, off);
        }
        l0 = l0 * al0 + ps0;
        l1 = l1 * al1 + ps1;
        m0 = mn0;
        m1 = mn1;
#pragma unroll
        for (int nt = 0; nt < 16; nt++) {
            o[nt][0] *= al0;
            o[nt][1] *= al0;
            o[nt][2] *= al1;
            o[nt][3] *= al1;
        }

        // ---- stage P to smem (tf32 bits) ----
#pragma unroll
        for (int nt = 0; nt < 8; nt++) {
            uint2 lo = {f2tf32(s[nt][0]), f2tf32(s[nt][1])};
            uint2 hi = {f2tf32(s[nt][2]), f2tf32(s[nt][3])};
            *(uint2*)&Ps[(rb + g) * LDP + nt * 8 + 2 * c]     = lo;
            *(uint2*)&Ps[(rb + g + 8) * LDP + nt * 8 + 2 * c] = hi;
        }
        __syncwarp();

        // ---- O += P @ V : 8 k-steps over keys, 16 n-tiles over head dim ----
#pragma unroll
        for (int k = 0; k < 8; k++) {
            uint32_t a[4];
            const uint32_t* pr = Ps + (rb + g) * LDP + k * 8 + c;
            a[0] = pr[0];
            a[2] = pr[4];
            a[1] = pr[8 * LDP];
            a[3] = pr[8 * LDP + 4];
#pragma unroll
            for (int nt = 0; nt < 16; nt++) {
                const uint32_t* vr = Vs + (k * 8 + c) * LDB + nt * 8 + g;
                mma_tf32(o[nt], a, vr[0], vr[4 * LDB]);
            }
        }
    }

    // ---- normalize + write out ----
    float inv0 = 1.0f / l0;
    float inv1 = 1.0f / l1;
    float* orow0 = outg + ((size_t)b * TT + qt * 128 + rb + g) * HH;
    float* orow1 = orow0 + 8 * HH;
#pragma unroll
    for (int nt = 0; nt < 16; nt++) {
        int col = nt * 8 + 2 * c;
        float2 lo = {o[nt][0] * inv0, o[nt][1] * inv0};
        float2 hi = {o[nt][2] * inv1, o[nt][3] * inv1};
        *(float2*)(orow0 + col) = lo;
        *(float2*)(orow1 + col) = hi;
    }
}

// ===========================================================================
extern "C" void kernel_launch(void* const* d_in, const int* in_sizes, int n_in,
                              void* d_out, int out_size)
{
    const float* x  = (const float*)d_in[0];
    const float* Wk = (const float*)d_in[1];
    const float* Wq = (const float*)d_in[2];
    const float* Wv = (const float*)d_in[3];

    float* out  = (float*)d_out;
    float* kout = out + (size_t)BTH;
    float* vout = out + 2 * (size_t)BTH;

    cudaFuncSetAttribute(proj_mma, cudaFuncAttributeMaxDynamicSharedMemorySize, PROJ_SMEM);
    cudaFuncSetAttribute(attn_mma, cudaFuncAttributeMaxDynamicSharedMemorySize, ATTN_SMEM);

    proj_mma<<<1024, 256, PROJ_SMEM>>>(x, Wk, Wq, Wv, kout, vout);
    attn_mma<<<dim3(2, 512), 256, ATTN_SMEM>>>(kout, vout, out);
}

// round 4
// speedup vs baseline: 2.8650x; 1.0170x over previous
#include <cuda_runtime.h>
#include <cstdint>

#define BB 512
#define TT 256
#define CC 128
#define HH 128
#define BTH (BB * TT * HH)   // 16,777,216

// Scratch for q projection (allocation-free rule: __device__ global)
__device__ float g_q[(size_t)BTH];

// fp32 -> tf32 round-to-nearest (unbiased)
__device__ __forceinline__ uint32_t f2tf32(float f) {
    uint32_t r;
    asm("cvt.rna.tf32.f32 %0, %1;" : "=r"(r) : "f"(f));
    return r;
}
__device__ __forceinline__ uint32_t smem_u32(const void* p) {
    uint32_t a;
    asm("{ .reg .u64 t; cvta.to.shared.u64 t, %1; cvt.u32.u64 %0, t; }" : "=r"(a) : "l"(p));
    return a;
}
__device__ __forceinline__ void cp_async16(uint32_t dst, const void* src) {
    asm volatile("cp.async.cg.shared.global [%0], [%1], 16;" :: "r"(dst), "l"(src));
}
#define CP_COMMIT() asm volatile("cp.async.commit_group;" ::: "memory")
#define CP_WAIT0()  asm volatile("cp.async.wait_group 0;" ::: "memory")

// m16n8k8 tf32 MMA, accumulate in place
__device__ __forceinline__ void mma_tf32(float acc[4], const uint32_t a[4],
                                         uint32_t b0, uint32_t b1) {
    asm volatile(
        "mma.sync.aligned.m16n8k8.row.col.f32.tf32.tf32.f32 "
        "{%0,%1,%2,%3}, {%4,%5,%6,%7}, {%8,%9}, {%0,%1,%2,%3};"
        : "+f"(acc[0]), "+f"(acc[1]), "+f"(acc[2]), "+f"(acc[3])
        : "r"(a[0]), "r"(a[1]), "r"(a[2]), "r"(a[3]), "r"(b0), "r"(b1));
}

// ===========================================================================
// Kernel 1: projection, K+Q phases fused (shared A-frags), then V phase.
// CTA: 128x128x128. 8 warps = 4 m-groups x 2 n-groups.
// smem: xs[128][132], ws0[128][136] (Wk then Wv), ws1[128][136] (Wq).
// ===========================================================================
#define LDA 132
#define LDB 136
#define PROJ_SMEM ((128 * LDA + 2 * 128 * LDB) * 4)

__device__ __forceinline__ void load_w_smem(const float* __restrict__ W,
                                            uint32_t* __restrict__ ws, int tid) {
    const float4* wg = (const float4*)W;
#pragma unroll
    for (int j = 0; j < 16; j++) {
        int i4 = tid + j * 256;
        float4 v = wg[i4];
        int row = i4 >> 5;
        int c4  = (i4 & 31) * 4;
        uint4 t = {f2tf32(v.x), f2tf32(v.y), f2tf32(v.z), f2tf32(v.w)};
        *(uint4*)&ws[row * LDB + c4] = t;
    }
}

__device__ __forceinline__ void epilogue_store(const float acc[2][8][4],
                                               float* __restrict__ outp,
                                               int mbase, int nbase, int g, int c) {
#pragma unroll
    for (int mt = 0; mt < 2; mt++) {
        int row = mbase + mt * 16 + g;
#pragma unroll
        for (int nt = 0; nt < 8; nt++) {
            int col = nbase + nt * 8 + 2 * c;
            float2 lo = {acc[mt][nt][0], acc[mt][nt][1]};
            float2 hi = {acc[mt][nt][2], acc[mt][nt][3]};
            *(float2*)(outp + (size_t)row * HH + col)       = lo;
            *(float2*)(outp + (size_t)(row + 8) * HH + col) = hi;
        }
    }
}

__global__ void __launch_bounds__(256, 1)
proj_mma(const float* __restrict__ x,
         const float* __restrict__ Wk,
         const float* __restrict__ Wq,
         const float* __restrict__ Wv,
         float* __restrict__ kout,
         float* __restrict__ vout)
{
    extern __shared__ uint32_t sm[];
    uint32_t* xs  = sm;
    uint32_t* ws0 = sm + 128 * LDA;
    uint32_t* ws1 = ws0 + 128 * LDB;

    const int tid  = threadIdx.x;
    const int tile = blockIdx.x;
    const int w    = tid >> 5;
    const int lane = tid & 31;
    const int g    = lane >> 2;
    const int c    = lane & 3;
    const int mbase = (w >> 1) * 32;
    const int nbase = (w & 1) * 64;

    // Load x tile -> xs (tf32)
    {
        const float4* xg = (const float4*)(x + (size_t)tile * 128 * CC);
#pragma unroll
        for (int j = 0; j < 16; j++) {
            int i4 = tid + j * 256;
            float4 v = xg[i4];
            int row = i4 >> 5;
            int c4  = (i4 & 31) * 4;
            uint4 t = {f2tf32(v.x), f2tf32(v.y), f2tf32(v.z), f2tf32(v.w)};
            *(uint4*)&xs[row * LDA + c4] = t;
        }
    }
    load_w_smem(Wk, ws0, tid);
    load_w_smem(Wq, ws1, tid);
    __syncthreads();

    // ---- fused K+Q mma loop ----
    float ak[2][8][4], aq[2][8][4];
#pragma unroll
    for (int mt = 0; mt < 2; mt++)
#pragma unroll
        for (int nt = 0; nt < 8; nt++)
#pragma unroll
            for (int e = 0; e < 4; e++) { ak[mt][nt][e] = 0.0f; aq[mt][nt][e] = 0.0f; }

#pragma unroll
    for (int k = 0; k < 16; k++) {
        uint32_t a[2][4];
#pragma unroll
        for (int mt = 0; mt < 2; mt++) {
            const uint32_t* xr = xs + (mbase + mt * 16 + g) * LDA + k * 8 + c;
            a[mt][0] = xr[0];
            a[mt][2] = xr[4];
            a[mt][1] = xr[8 * LDA];
            a[mt][3] = xr[8 * LDA + 4];
        }
#pragma unroll
        for (int nt = 0; nt < 8; nt++) {
            const uint32_t* wr0 = ws0 + (k * 8 + c) * LDB + nbase + nt * 8 + g;
            const uint32_t* wr1 = ws1 + (k * 8 + c) * LDB + nbase + nt * 8 + g;
            uint32_t bk0 = wr0[0], bk1 = wr0[4 * LDB];
            uint32_t bq0 = wr1[0], bq1 = wr1[4 * LDB];
            mma_tf32(ak[0][nt], a[0], bk0, bk1);
            mma_tf32(ak[1][nt], a[1], bk0, bk1);
            mma_tf32(aq[0][nt], a[0], bq0, bq1);
            mma_tf32(aq[1][nt], a[1], bq0, bq1);
        }
    }
    __syncthreads();   // ws0 free (Wk consumed)

    // K epilogue (STG) then Wv -> ws0 (LDG overlaps STG drain) then Q epilogue
    epilogue_store(ak, kout + (size_t)tile * 128 * HH, mbase, nbase, g, c);
    load_w_smem(Wv, ws0, tid);
    epilogue_store(aq, g_q + (size_t)tile * 128 * HH, mbase, nbase, g, c);
    __syncthreads();

    // ---- V phase ----
    float av[2][8][4];
#pragma unroll
    for (int mt = 0; mt < 2; mt++)
#pragma unroll
        for (int nt = 0; nt < 8; nt++)
#pragma unroll
            for (int e = 0; e < 4; e++) av[mt][nt][e] = 0.0f;

#pragma unroll
    for (int k = 0; k < 16; k++) {
        uint32_t a[2][4];
#pragma unroll
        for (int mt = 0; mt < 2; mt++) {
            const uint32_t* xr = xs + (mbase + mt * 16 + g) * LDA + k * 8 + c;
            a[mt][0] = xr[0];
            a[mt][2] = xr[4];
            a[mt][1] = xr[8 * LDA];
            a[mt][3] = xr[8 * LDA + 4];
        }
#pragma unroll
        for (int nt = 0; nt < 8; nt++) {
            const uint32_t* wr = ws0 + (k * 8 + c) * LDB + nbase + nt * 8 + g;
            uint32_t b0 = wr[0], b1 = wr[4 * LDB];
            mma_tf32(av[0][nt], a[0], b0, b1);
            mma_tf32(av[1][nt], a[1], b0, b1);
        }
    }
    epilogue_store(av, vout + (size_t)tile * 128 * HH, mbase, nbase, g, c);
}

// ===========================================================================
// Kernel 2: causal flash attention, cp.async pipelined.
// Grid (2 q-tiles, 512 batches), 256 threads. Warp w: q-rows w*16..+15.
// K: single buffer (prefetch overlaps softmax+PV). V: double buffer
// (prefetch overlaps full iteration). K/V stored raw fp32; B-frags
// converted to tf32 in registers. Q pre-scaled by C^-0.5 * log2(e).
// smem: Qs[128][132] + Ks[64][132] + Vs[2][64][136] + Ps[128][68] = 205.8KB
// ===========================================================================
#define LDV 136
#define LDP 68
#define VSTRIDE (64 * LDV)
#define ATTN_SMEM ((128 * LDA + 64 * LDA + 2 * VSTRIDE + 128 * LDP) * 4)
#define NEG_BIG (-1.0e30f)

__device__ __forceinline__ void cp_tile(uint32_t dst_base, const float* __restrict__ gsrc,
                                        int ld, int tid) {
#pragma unroll
    for (int j = 0; j < 8; j++) {
        int i4  = tid + j * 256;
        int row = i4 >> 5;
        int c4  = (i4 & 31) * 4;
        cp_async16(dst_base + (uint32_t)(row * ld + c4) * 4u,
                   (const char*)gsrc + (size_t)i4 * 16);
    }
}

__global__ void __launch_bounds__(256, 1)
attn_mma(const float* __restrict__ kg,
         const float* __restrict__ vg,
         float* __restrict__ outg)
{
    extern __shared__ uint32_t sm[];
    uint32_t* Qs = sm;                       // [128][132] tf32 (pre-scaled)
    uint32_t* Ks = Qs + 128 * LDA;           // [64][132] raw fp32
    uint32_t* Vs = Ks + 64 * LDA;            // [2][64][136] raw fp32
    uint32_t* Ps = Vs + 2 * VSTRIDE;         // [128][68] tf32

    const int tid  = threadIdx.x;
    const int qt   = blockIdx.x;             // 0..1
    const int b    = blockIdx.y;             // 0..511
    const int w    = tid >> 5;
    const int lane = tid & 31;
    const int g    = lane >> 2;
    const int c    = lane & 3;
    const int rb   = w * 16;
    // scale * log2(e): softmax computed base-2
    const float QS = 0.08838834764831845f * 1.4426950408889634f;

    const uint32_t ks_addr = smem_u32(Ks);
    const uint32_t vs_addr = smem_u32(Vs);

    const float* kbase = kg + (size_t)b * TT * HH;
    const float* vbase = vg + (size_t)b * TT * HH;
    const int nkt = qt ? 4 : 2;

    // Prologue: async K0, V0; then Q load (overlaps the cp.asyncs)
    cp_tile(ks_addr, kbase, LDA, tid);
    CP_COMMIT();
    cp_tile(vs_addr, vbase, LDV, tid);
    CP_COMMIT();
    {
        const float4* qg4 = (const float4*)(g_q + ((size_t)b * TT + qt * 128) * HH);
#pragma unroll
        for (int j = 0; j < 16; j++) {
            int i4 = tid + j * 256;
            float4 v = qg4[i4];
            int row = i4 >> 5;
            int c4  = (i4 & 31) * 4;
            uint4 t = {f2tf32(v.x * QS), f2tf32(v.y * QS), f2tf32(v.z * QS), f2tf32(v.w * QS)};
            *(uint4*)&Qs[row * LDA + c4] = t;
        }
    }

    float m0 = NEG_BIG, m1 = NEG_BIG, l0 = 0.0f, l1 = 0.0f;
    float o[16][4];
#pragma unroll
    for (int nt = 0; nt < 16; nt++)
#pragma unroll
        for (int e = 0; e < 4; e++) o[nt][e] = 0.0f;

    const int row0 = qt * 128 + rb + g;
    const int row1 = row0 + 8;

    for (int st = 0; st < nkt; st++) {
        CP_WAIT0();            // K_st and V_st landed (this thread)
        __syncthreads();       // all threads' tiles visible; PV_{st-1} fully done

        // Prefetch V_{st+1} into the other buffer (overlaps full iteration)
        if (st + 1 < nkt) {
            cp_tile(vs_addr + (uint32_t)(((st + 1) & 1) * VSTRIDE) * 4u,
                    vbase + (size_t)(st + 1) * 64 * HH, LDV, tid);
            CP_COMMIT();
        }

        // ---- S = Q K^T (B-frags cvt in regs) ----
        float s[8][4];
#pragma unroll
        for (int nt = 0; nt < 8; nt++)
#pragma unroll
            for (int e = 0; e < 4; e++) s[nt][e] = 0.0f;

#pragma unroll
        for (int k = 0; k < 16; k++) {
            uint32_t a[4];
            const uint32_t* qr = Qs + (rb + g) * LDA + k * 8 + c;
            a[0] = qr[0];
            a[2] = qr[4];
            a[1] = qr[8 * LDA];
            a[3] = qr[8 * LDA + 4];
#pragma unroll
            for (int nt = 0; nt < 8; nt++) {
                const uint32_t* kr = Ks + (nt * 8 + g) * LDA + k * 8 + c;
                uint32_t b0 = f2tf32(__uint_as_float(kr[0]));
                uint32_t b1 = f2tf32(__uint_as_float(kr[4]));
                mma_tf32(s[nt], a, b0, b1);
            }
        }
        __syncthreads();       // all warps done reading Ks -> K buffer free

        // Prefetch K_{st+1} (overlaps softmax + PV)
        if (st + 1 < nkt) {
            cp_tile(ks_addr, kbase + (size_t)(st + 1) * 64 * HH, LDA, tid);
            CP_COMMIT();
        }

        // ---- causal mask + online softmax (base 2; Q pre-scaled) ----
        float mx0 = NEG_BIG, mx1 = NEG_BIG;
#pragma unroll
        for (int nt = 0; nt < 8; nt++) {
            int k0 = st * 64 + nt * 8 + 2 * c;
            s[nt][0] = (k0     <= row0) ? s[nt][0] : NEG_BIG;
            s[nt][1] = (k0 + 1 <= row0) ? s[nt][1] : NEG_BIG;
            s[nt][2] = (k0     <= row1) ? s[nt][2] : NEG_BIG;
            s[nt][3] = (k0 + 1 <= row1) ? s[nt][3] : NEG_BIG;
            mx0 = fmaxf(mx0, fmaxf(s[nt][0], s[nt][1]));
            mx1 = fmaxf(mx1, fmaxf(s[nt][2], s[nt][3]));
        }
#pragma unroll
        for (int off = 1; off < 4; off <<= 1) {
            mx0 = fmaxf(mx0, __shfl_xor_sync(0xffffffffu, mx0, off));
            mx1 = fmaxf(mx1, __shfl_xor_sync(0xffffffffu, mx1, off));
        }
        float mn0 = fmaxf(m0, mx0);
        float mn1 = fmaxf(m1, mx1);
        float al0 = exp2f(m0 - mn0);
        float al1 = exp2f(m1 - mn1);
        float ps0 = 0.0f, ps1 = 0.0f;
#pragma unroll
        for (int nt = 0; nt < 8; nt++) {
            s[nt][0] = exp2f(s[nt][0] - mn0);
            s[nt][1] = exp2f(s[nt][1] - mn0);
            s[nt][2] = exp2f(s[nt][2] - mn1);
            s[nt][3] = exp2f(s[nt][3] - mn1);
            ps0 += s[nt][0] + s[nt][1];
            ps1 += s[nt][2] + s[nt][3];
        }
#pragma unroll
        for (int off = 1; off < 4; off <<= 1) {
            ps0 += __shfl_xor_sync(0xffffffffu, ps0, off);
            ps1 += __shfl_xor_sync(0xffffffffu, ps1, off);
        }
        l0 = l0 * al0 + ps0;
        l1 = l1 * al1 + ps1;
        m0 = mn0;
        m1 = mn1;
#pragma unroll
        for (int nt = 0; nt < 16; nt++) {
            o[nt][0] *= al0;
            o[nt][1] *= al0;
            o[nt][2] *= al1;
            o[nt][3] *= al1;
        }

        // ---- stage P (tf32) ----
#pragma unroll
        for (int nt = 0; nt < 8; nt++) {
            uint2 lo = {f2tf32(s[nt][0]), f2tf32(s[nt][1])};
            uint2 hi = {f2tf32(s[nt][2]), f2tf32(s[nt][3])};
            *(uint2*)&Ps[(rb + g) * LDP + nt * 8 + 2 * c]     = lo;
            *(uint2*)&Ps[(rb + g + 8) * LDP + nt * 8 + 2 * c] = hi;
        }
        __syncwarp();

        // ---- O += P @ V (B-frags cvt in regs) ----
        const uint32_t* Vcur = Vs + (st & 1) * VSTRIDE;
#pragma unroll
        for (int k = 0; k < 8; k++) {
            uint32_t a[4];
            const uint32_t* pr = Ps + (rb + g) * LDP + k * 8 + c;
            a[0] = pr[0];
            a[2] = pr[4];
            a[1] = pr[8 * LDP];
            a[3] = pr[8 * LDP + 4];
#pragma unroll
            for (int nt = 0; nt < 16; nt++) {
                const uint32_t* vr = Vcur + (k * 8 + c) * LDV + nt * 8 + g;
                uint32_t b0 = f2tf32(__uint_as_float(vr[0]));
                uint32_t b1 = f2tf32(__uint_as_float(vr[4 * LDV]));
                mma_tf32(o[nt], a, b0, b1);
            }
        }
    }

    // ---- normalize + write ----
    float inv0 = 1.0f / l0;
    float inv1 = 1.0f / l1;
    float* orow0 = outg + ((size_t)b * TT + qt * 128 + rb + g) * HH;
    float* orow1 = orow0 + 8 * HH;
#pragma unroll
    for (int nt = 0; nt < 16; nt++) {
        int col = nt * 8 + 2 * c;
        float2 lo = {o[nt][0] * inv0, o[nt][1] * inv0};
        float2 hi = {o[nt][2] * inv1, o[nt][3] * inv1};
        *(float2*)(orow0 + col) = lo;
        *(float2*)(orow1 + col) = hi;
    }
}

// ===========================================================================
extern "C" void kernel_launch(void* const* d_in, const int* in_sizes, int n_in,
                              void* d_out, int out_size)
{
    const float* x  = (const float*)d_in[0];
    const float* Wk = (const float*)d_in[1];
    const float* Wq = (const float*)d_in[2];
    const float* Wv = (const float*)d_in[3];

    float* out  = (float*)d_out;
    float* kout = out + (size_t)BTH;
    float* vout = out + 2 * (size_t)BTH;

    cudaFuncSetAttribute(proj_mma, cudaFuncAttributeMaxDynamicSharedMemorySize, PROJ_SMEM);
    cudaFuncSetAttribute(attn_mma, cudaFuncAttributeMaxDynamicSharedMemorySize, ATTN_SMEM);

    proj_mma<<<1024, 256, PROJ_SMEM>>>(x, Wk, Wq, Wv, kout, vout);
    attn_mma<<<dim3(2, 512), 256, ATTN_SMEM>>>(kout, vout, out);
}

// round 5
// speedup vs baseline: 4.0902x; 1.4276x over previous
#include <cuda_runtime.h>
#include <cuda_fp16.h>
#include <cstdint>

#define BB 512
#define TT 256
#define CC 128
#define HH 128
#define BTH (BB * TT * HH)   // 16,777,216

// fp16 scratch (allocation-free rule: __device__ globals)
__device__ __half g_qh[(size_t)BTH];  // q * QS, [b][t][h]
__device__ __half g_kh[(size_t)BTH];  // k,      [b][t][h]
__device__ __half g_vt[(size_t)BTH];  // v,      [b][h][t]  (transposed)

__device__ __forceinline__ uint32_t h2bits(float a, float b) {
    __half2 h = __floats2half2_rn(a, b);
    return *(uint32_t*)&h;
}
__device__ __forceinline__ uint32_t smem_u32(const void* p) {
    uint32_t a;
    asm("{ .reg .u64 t; cvta.to.shared.u64 t, %1; cvt.u32.u64 %0, t; }" : "=r"(a) : "l"(p));
    return a;
}
__device__ __forceinline__ void cp_async16(uint32_t dst, const void* src) {
    asm volatile("cp.async.cg.shared.global [%0], [%1], 16;" :: "r"(dst), "l"(src));
}
#define CP_COMMIT() asm volatile("cp.async.commit_group;" ::: "memory")
#define CP_WAIT0()  asm volatile("cp.async.wait_group 0;" ::: "memory")

// m16n8k16 fp16 MMA, fp32 accumulate in place
__device__ __forceinline__ void mma_f16(float acc[4], const uint32_t a[4],
                                        uint32_t b0, uint32_t b1) {
    asm volatile(
        "mma.sync.aligned.m16n8k16.row.col.f32.f16.f16.f32 "
        "{%0,%1,%2,%3}, {%4,%5,%6,%7}, {%8,%9}, {%0,%1,%2,%3};"
        : "+f"(acc[0]), "+f"(acc[1]), "+f"(acc[2]), "+f"(acc[3])
        : "r"(a[0]), "r"(a[1]), "r"(a[2]), "r"(a[3]), "r"(b0), "r"(b1));
}

// scale * log2(e): softmax computed base-2; folded into q at projection time
#define QSCALE (0.08838834764831845f * 1.4426950408889634f)

// ===========================================================================
// Kernel 1: projection (fp16 mma).  {k,q,v} = x @ {Wk,Wq,Wv}
// CTA: 128x128x128. 8 warps = 4 m-groups x 2 n-groups, 2x8 mma microtile.
// smem (halves, stride 136): xs[128][136], ws0[128][136], ws1[128][136]
// ws* hold W TRANSPOSED ([n][k], k-contiguous) as the mma B operand needs.
// Emits fp32 k,v to d_out regions + fp16 q(scaled)/k/v(transposed) scratch.
// ===========================================================================
#define LDH 136
#define PROJ_SMEM (3 * 128 * LDH * 2)

__device__ __forceinline__ void load_w_t(const float* __restrict__ W,
                                         __half* __restrict__ ws, int tid) {
#pragma unroll
    for (int j = 0; j < 16; j++) {
        int i  = tid + j * 256;        // 0..4095 quads
        int n  = i & 127;
        int kq = i >> 7;               // 0..31
        float w0 = W[(kq * 4 + 0) * HH + n];
        float w1 = W[(kq * 4 + 1) * HH + n];
        float w2 = W[(kq * 4 + 2) * HH + n];
        float w3 = W[(kq * 4 + 3) * HH + n];
        uint2 p = {h2bits(w0, w1), h2bits(w2, w3)};
        *(uint2*)&ws[n * LDH + kq * 4] = p;
    }
}

__global__ void __launch_bounds__(256, 1)
proj_mma(const float* __restrict__ x,
         const float* __restrict__ Wk,
         const float* __restrict__ Wq,
         const float* __restrict__ Wv,
         float* __restrict__ kout,
         float* __restrict__ vout)
{
    extern __shared__ __half smh[];
    __half* xs  = smh;
    __half* ws0 = smh + 128 * LDH;
    __half* ws1 = ws0 + 128 * LDH;

    const int tid  = threadIdx.x;
    const int tile = blockIdx.x;
    const int w    = tid >> 5;
    const int lane = tid & 31;
    const int g    = lane >> 2;
    const int c    = lane & 3;
    const int mbase = (w >> 1) * 32;
    const int nbase = (w & 1) * 64;

    // x tile -> xs (fp16, row-major)
    {
        const float4* xg = (const float4*)(x + (size_t)tile * 128 * CC);
#pragma unroll
        for (int j = 0; j < 16; j++) {
            int i4 = tid + j * 256;
            float4 v = xg[i4];
            int row = i4 >> 5;
            int c4  = (i4 & 31) * 4;
            uint2 p = {h2bits(v.x, v.y), h2bits(v.z, v.w)};
            *(uint2*)&xs[row * LDH + c4] = p;
        }
    }
    load_w_t(Wk, ws0, tid);
    load_w_t(Wq, ws1, tid);
    __syncthreads();

    // ---- fused K+Q mma (8 k-steps of k16) ----
    float ak[2][8][4], aq[2][8][4];
#pragma unroll
    for (int mt = 0; mt < 2; mt++)
#pragma unroll
        for (int nt = 0; nt < 8; nt++)
#pragma unroll
            for (int e = 0; e < 4; e++) { ak[mt][nt][e] = 0.0f; aq[mt][nt][e] = 0.0f; }

#pragma unroll
    for (int kk = 0; kk < 8; kk++) {
        uint32_t a[2][4];
#pragma unroll
        for (int mt = 0; mt < 2; mt++) {
            const __half* xr = xs + (mbase + mt * 16 + g) * LDH + kk * 16 + 2 * c;
            a[mt][0] = *(const uint32_t*)(xr);
            a[mt][1] = *(const uint32_t*)(xr + 8 * LDH);
            a[mt][2] = *(const uint32_t*)(xr + 8);
            a[mt][3] = *(const uint32_t*)(xr + 8 * LDH + 8);
        }
#pragma unroll
        for (int nt = 0; nt < 8; nt++) {
            const __half* w0p = ws0 + (nbase + nt * 8 + g) * LDH + kk * 16 + 2 * c;
            const __half* w1p = ws1 + (nbase + nt * 8 + g) * LDH + kk * 16 + 2 * c;
            uint32_t bk0 = *(const uint32_t*)(w0p), bk1 = *(const uint32_t*)(w0p + 8);
            uint32_t bq0 = *(const uint32_t*)(w1p), bq1 = *(const uint32_t*)(w1p + 8);
            mma_f16(ak[0][nt], a[0], bk0, bk1);
            mma_f16(ak[1][nt], a[1], bk0, bk1);
            mma_f16(aq[0][nt], a[0], bq0, bq1);
            mma_f16(aq[1][nt], a[1], bq0, bq1);
        }
    }
    __syncthreads();   // ws0 free

    // K epilogue (fp32 + fp16), Wv load overlaps, Q epilogue (fp16 scaled)
#pragma unroll
    for (int mt = 0; mt < 2; mt++) {
#pragma unroll
        for (int nt = 0; nt < 8; nt++) {
            int row = tile * 128 + mbase + mt * 16 + g;
            int col = nbase + nt * 8 + 2 * c;
            const float* kk4 = ak[mt][nt];
            *(float2*)(kout + (size_t)row * HH + col)       = make_float2(kk4[0], kk4[1]);
            *(float2*)(kout + (size_t)(row + 8) * HH + col) = make_float2(kk4[2], kk4[3]);
            *(uint32_t*)&g_kh[(size_t)row * HH + col]       = h2bits(kk4[0], kk4[1]);
            *(uint32_t*)&g_kh[(size_t)(row + 8) * HH + col] = h2bits(kk4[2], kk4[3]);
        }
    }
    load_w_t(Wv, ws0, tid);
#pragma unroll
    for (int mt = 0; mt < 2; mt++) {
#pragma unroll
        for (int nt = 0; nt < 8; nt++) {
            int row = tile * 128 + mbase + mt * 16 + g;
            int col = nbase + nt * 8 + 2 * c;
            const float* q4 = aq[mt][nt];
            *(uint32_t*)&g_qh[(size_t)row * HH + col]       = h2bits(q4[0] * QSCALE, q4[1] * QSCALE);
            *(uint32_t*)&g_qh[(size_t)(row + 8) * HH + col] = h2bits(q4[2] * QSCALE, q4[3] * QSCALE);
        }
    }
    __syncthreads();

    // ---- V phase ----
    float av[2][8][4];
#pragma unroll
    for (int mt = 0; mt < 2; mt++)
#pragma unroll
        for (int nt = 0; nt < 8; nt++)
#pragma unroll
            for (int e = 0; e < 4; e++) av[mt][nt][e] = 0.0f;

#pragma unroll
    for (int kk = 0; kk < 8; kk++) {
        uint32_t a[2][4];
#pragma unroll
        for (int mt = 0; mt < 2; mt++) {
            const __half* xr = xs + (mbase + mt * 16 + g) * LDH + kk * 16 + 2 * c;
            a[mt][0] = *(const uint32_t*)(xr);
            a[mt][1] = *(const uint32_t*)(xr + 8 * LDH);
            a[mt][2] = *(const uint32_t*)(xr + 8);
            a[mt][3] = *(const uint32_t*)(xr + 8 * LDH + 8);
        }
#pragma unroll
        for (int nt = 0; nt < 8; nt++) {
            const __half* wp = ws0 + (nbase + nt * 8 + g) * LDH + kk * 16 + 2 * c;
            uint32_t b0 = *(const uint32_t*)(wp), b1 = *(const uint32_t*)(wp + 8);
            mma_f16(av[0][nt], a[0], b0, b1);
            mma_f16(av[1][nt], a[1], b0, b1);
        }
    }

    // V epilogue: fp32 + fp16 TRANSPOSED ([b][h][t])
    {
        const int tb = tile >> 1;               // batch
        const size_t vb = (size_t)tb * 128 * 256;
#pragma unroll
        for (int mt = 0; mt < 2; mt++) {
#pragma unroll
            for (int nt = 0; nt < 8; nt++) {
                int rloc = mbase + mt * 16 + g;
                int row  = tile * 128 + rloc;
                int lt   = (tile & 1) * 128 + rloc;   // token within batch
                int col  = nbase + nt * 8 + 2 * c;
                const float* v4 = av[mt][nt];
                *(float2*)(vout + (size_t)row * HH + col)       = make_float2(v4[0], v4[1]);
                *(float2*)(vout + (size_t)(row + 8) * HH + col) = make_float2(v4[2], v4[3]);
                g_vt[vb + (size_t)col * 256 + lt]           = __float2half_rn(v4[0]);
                g_vt[vb + (size_t)(col + 1) * 256 + lt]     = __float2half_rn(v4[1]);
                g_vt[vb + (size_t)col * 256 + lt + 8]       = __float2half_rn(v4[2]);
                g_vt[vb + (size_t)(col + 1) * 256 + lt + 8] = __float2half_rn(v4[3]);
            }
        }
    }
}

// ===========================================================================
// Kernel 2: causal flash attention, fp16 mma, full double-buffered cp.async.
// Grid (2 q-tiles, 512 batches), 256 thr. Warp w: q-rows w*16..+15.
// Q fragments in registers (loaded once from g_qh, pre-scaled).
// smem (halves): Ks[2][64][136], Vt[2][128][72], Ps[128][72]  = 90.1KB
// ===========================================================================
#define LKH 136
#define LVH 72
#define LPH 72
#define KBUF (64 * LKH)
#define VBUF (128 * LVH)
#define ATTN_SMEM ((2 * KBUF + 2 * VBUF + 128 * LPH) * 2)
#define NEG_BIG (-1.0e30f)

__global__ void __launch_bounds__(256, 1)
attn_mma(float* __restrict__ outg)
{
    extern __shared__ __half smh[];
    __half* Ks = smh;                 // [2][64][136]
    __half* Vt = Ks + 2 * KBUF;       // [2][128][72]
    __half* Ps = Vt + 2 * VBUF;       // [128][72]

    const int tid  = threadIdx.x;
    const int qt   = blockIdx.x;      // 0..1
    const int b    = blockIdx.y;      // 0..511
    const int w    = tid >> 5;
    const int lane = tid & 31;
    const int g    = lane >> 2;
    const int c    = lane & 3;
    const int rb   = w * 16;

    const uint32_t ks_a = smem_u32(Ks);
    const uint32_t vt_a = smem_u32(Vt);

    const __half* kh = g_kh + (size_t)b * TT * HH;      // [t][h]
    const __half* vt = g_vt + (size_t)b * 128 * 256;    // [h][t]
    const int nkt = qt ? 4 : 2;

    // ---- async copy helpers (per-stage: K 64x256B, Vt 128x128B) ----
    auto cp_stage = [&](int st) {
        uint32_t kd = ks_a + (uint32_t)((st & 1) * KBUF) * 2u;
        uint32_t vd = vt_a + (uint32_t)((st & 1) * VBUF) * 2u;
#pragma unroll
        for (int j = 0; j < 4; j++) {
            int i4 = tid + j * 256;
            int kr = i4 >> 4, kc = i4 & 15;          // K: row, 16B-chunk
            cp_async16(kd + (uint32_t)(kr * LKH + kc * 8) * 2u,
                       kh + (size_t)(st * 64 + kr) * HH + kc * 8);
            int vr = i4 >> 3, vc = i4 & 7;           // Vt: head-row, chunk
            cp_async16(vd + (uint32_t)(vr * LVH + vc * 8) * 2u,
                       vt + (size_t)vr * 256 + st * 64 + vc * 8);
        }
        CP_COMMIT();
    };

    cp_stage(0);

    // ---- Q fragments -> registers (8 k-steps x 4 regs) ----
    uint32_t aq[8][4];
    {
        const __half* q0 = g_qh + ((size_t)b * TT + qt * 128 + rb + g) * HH + 2 * c;
        const __half* q1 = q0 + 8 * HH;
#pragma unroll
        for (int kk = 0; kk < 8; kk++) {
            aq[kk][0] = *(const uint32_t*)(q0 + kk * 16);
            aq[kk][1] = *(const uint32_t*)(q1 + kk * 16);
            aq[kk][2] = *(const uint32_t*)(q0 + kk * 16 + 8);
            aq[kk][3] = *(const uint32_t*)(q1 + kk * 16 + 8);
        }
    }

    float m0 = NEG_BIG, m1 = NEG_BIG, l0 = 0.0f, l1 = 0.0f;
    float o[16][4];
#pragma unroll
    for (int nt = 0; nt < 16; nt++)
#pragma unroll
        for (int e = 0; e < 4; e++) o[nt][e] = 0.0f;

    const int row0 = qt * 128 + rb + g;
    const int row1 = row0 + 8;

    for (int st = 0; st < nkt; st++) {
        CP_WAIT0();            // stage st landed (this thread)
        __syncthreads();       // visible to all; prev compute done (buffers free)
        if (st + 1 < nkt) cp_stage(st + 1);   // overlaps this iteration

        const __half* Kb = Ks + (st & 1) * KBUF;
        const __half* Vb = Vt + (st & 1) * VBUF;

        // ---- S = Q K^T ----
        float s[8][4];
#pragma unroll
        for (int nt = 0; nt < 8; nt++)
#pragma unroll
            for (int e = 0; e < 4; e++) s[nt][e] = 0.0f;

#pragma unroll
        for (int kk = 0; kk < 8; kk++) {
#pragma unroll
            for (int nt = 0; nt < 8; nt++) {
                const __half* kr = Kb + (nt * 8 + g) * LKH + kk * 16 + 2 * c;
                uint32_t b0 = *(const uint32_t*)(kr);
                uint32_t b1 = *(const uint32_t*)(kr + 8);
                mma_f16(s[nt], aq[kk], b0, b1);
            }
        }

        // ---- causal mask + online softmax (base 2, Q pre-scaled) ----
        float mx0 = NEG_BIG, mx1 = NEG_BIG;
#pragma unroll
        for (int nt = 0; nt < 8; nt++) {
            int k0 = st * 64 + nt * 8 + 2 * c;
            s[nt][0] = (k0     <= row0) ? s[nt][0] : NEG_BIG;
            s[nt][1] = (k0 + 1 <= row0) ? s[nt][1] : NEG_BIG;
            s[nt][2] = (k0     <= row1) ? s[nt][2] : NEG_BIG;
            s[nt][3] = (k0 + 1 <= row1) ? s[nt][3] : NEG_BIG;
            mx0 = fmaxf(mx0, fmaxf(s[nt][0], s[nt][1]));
            mx1 = fmaxf(mx1, fmaxf(s[nt][2], s[nt][3]));
        }
#pragma unroll
        for (int off = 1; off < 4; off <<= 1) {
            mx0 = fmaxf(mx0, __shfl_xor_sync(0xffffffffu, mx0, off));
            mx1 = fmaxf(mx1, __shfl_xor_sync(0xffffffffu, mx1, off));
        }
        float mn0 = fmaxf(m0, mx0);
        float mn1 = fmaxf(m1, mx1);
        float al0 = exp2f(m0 - mn0);
        float al1 = exp2f(m1 - mn1);
        float ps0 = 0.0f, ps1 = 0.0f;
#pragma unroll
        for (int nt = 0; nt < 8; nt++) {
            s[nt][0] = exp2f(s[nt][0] - mn0);
            s[nt][1] = exp2f(s[nt][1] - mn0);
            s[nt][2] = exp2f(s[nt][2] - mn1);
            s[nt][3] = exp2f(s[nt][3] - mn1);
            ps0 += s[nt][0] + s[nt][1];
            ps1 += s[nt][2] + s[nt][3];
        }
#pragma unroll
        for (int off = 1; off < 4; off <<= 1) {
            ps0 += __shfl_xor_sync(0xffffffffu, ps0, off);
            ps1 += __shfl_xor_sync(0xffffffffu, ps1, off);
        }
        l0 = l0 * al0 + ps0;
        l1 = l1 * al1 + ps1;
        m0 = mn0;
        m1 = mn1;
#pragma unroll
        for (int nt = 0; nt < 16; nt++) {
            o[nt][0] *= al0;
            o[nt][1] *= al0;
            o[nt][2] *= al1;
            o[nt][3] *= al1;
        }

        // ---- stage P (fp16) ----
#pragma unroll
        for (int nt = 0; nt < 8; nt++) {
            *(uint32_t*)&Ps[(rb + g) * LPH + nt * 8 + 2 * c]     = h2bits(s[nt][0], s[nt][1]);
            *(uint32_t*)&Ps[(rb + g + 8) * LPH + nt * 8 + 2 * c] = h2bits(s[nt][2], s[nt][3]);
        }
        __syncwarp();   // P produced/consumed within this warp only

        // ---- O += P @ V (4 k-steps of k16, 16 head n-tiles) ----
#pragma unroll
        for (int kk = 0; kk < 4; kk++) {
            uint32_t a[4];
            const __half* pr = Ps + (rb + g) * LPH + kk * 16 + 2 * c;
            a[0] = *(const uint32_t*)(pr);
            a[1] = *(const uint32_t*)(pr + 8 * LPH);
            a[2] = *(const uint32_t*)(pr + 8);
            a[3] = *(const uint32_t*)(pr + 8 * LPH + 8);
#pragma unroll
            for (int nt = 0; nt < 16; nt++) {
                const __half* vr = Vb + (nt * 8 + g) * LVH + kk * 16 + 2 * c;
                uint32_t b0 = *(const uint32_t*)(vr);
                uint32_t b1 = *(const uint32_t*)(vr + 8);
                mma_f16(o[nt], a, b0, b1);
            }
        }
    }

    // ---- normalize + write ----
    float inv0 = 1.0f / l0;
    float inv1 = 1.0f / l1;
    float* orow0 = outg + ((size_t)b * TT + qt * 128 + rb + g) * HH;
    float* orow1 = orow0 + 8 * HH;
#pragma unroll
    for (int nt = 0; nt < 16; nt++) {
        int col = nt * 8 + 2 * c;
        *(float2*)(orow0 + col) = make_float2(o[nt][0] * inv0, o[nt][1] * inv0);
        *(float2*)(orow1 + col) = make_float2(o[nt][2] * inv1, o[nt][3] * inv1);
    }
}

// ===========================================================================
extern "C" void kernel_launch(void* const* d_in, const int* in_sizes, int n_in,
                              void* d_out, int out_size)
{
    const float* x  = (const float*)d_in[0];
    const float* Wk = (const float*)d_in[1];
    const float* Wq = (const float*)d_in[2];
    const float* Wv = (const float*)d_in[3];

    float* out  = (float*)d_out;
    float* kout = out + (size_t)BTH;
    float* vout = out + 2 * (size_t)BTH;

    cudaFuncSetAttribute(proj_mma, cudaFuncAttributeMaxDynamicSharedMemorySize, PROJ_SMEM);
    cudaFuncSetAttribute(attn_mma, cudaFuncAttributeMaxDynamicSharedMemorySize, ATTN_SMEM);

    proj_mma<<<1024, 256, PROJ_SMEM>>>(x, Wk, Wq, Wv, kout, vout);
    attn_mma<<<dim3(2, 512), 256, ATTN_SMEM>>>(out);
}

// round 7
// speedup vs baseline: 4.0955x; 1.0013x over previous
#include <cuda_runtime.h>
#include <cuda_fp16.h>
#include <cstdint>

#define BB 512
#define TT 256
#define CC 128
#define HH 128
#define BTH (BB * TT * HH)   // 16,777,216

// fp16 scratch (allocation-free rule: __device__ globals)
__device__ __half g_qh[(size_t)BTH];  // q * QS, [b][t][h]
__device__ __half g_kh[(size_t)BTH];  // k,      [b][t][h]
__device__ __half g_vt[(size_t)BTH];  // v,      [b][h][t]  (transposed)

__device__ __forceinline__ uint32_t h2bits(float a, float b) {
    __half2 h = __floats2half2_rn(a, b);
    return *(uint32_t*)&h;
}
__device__ __forceinline__ uint32_t smem_u32(const void* p) {
    uint32_t a;
    asm("{ .reg .u64 t; cvta.to.shared.u64 t, %1; cvt.u32.u64 %0, t; }" : "=r"(a) : "l"(p));
    return a;
}
__device__ __forceinline__ void cp_async16(uint32_t dst, const void* src) {
    asm volatile("cp.async.cg.shared.global [%0], [%1], 16;" :: "r"(dst), "l"(src));
}
#define CP_COMMIT() asm volatile("cp.async.commit_group;" ::: "memory")
#define CP_WAIT0()  asm volatile("cp.async.wait_group 0;" ::: "memory")

// m16n8k16 fp16 MMA, fp32 accumulate in place
__device__ __forceinline__ void mma_f16(float acc[4], const uint32_t a[4],
                                        uint32_t b0, uint32_t b1) {
    asm volatile(
        "mma.sync.aligned.m16n8k16.row.col.f32.f16.f16.f32 "
        "{%0,%1,%2,%3}, {%4,%5,%6,%7}, {%8,%9}, {%0,%1,%2,%3};"
        : "+f"(acc[0]), "+f"(acc[1]), "+f"(acc[2]), "+f"(acc[3])
        : "r"(a[0]), "r"(a[1]), "r"(a[2]), "r"(a[3]), "r"(b0), "r"(b1));
}

// scale * log2(e): softmax computed base-2; folded into q at projection time
#define QSCALE (0.08838834764831845f * 1.4426950408889634f)

// ===========================================================================
// Kernel 1: projection (fp16 mma).  {k,q,v} = x @ {Wk,Wq,Wv}
// CTA: 128x128x128. 8 warps = 4 m-groups x 2 n-groups, 2x8 microtile.
// smem (halves, stride 136): xs + ws0(Wk^T) + ws1(Wq^T) + ws2(Wv^T) = 139KB.
// All loads upfront (one sync). K+Q fused loop; V loop; v fp16 transposed
// output staged through smem (ws1 reused) for coalesced STG.
// ===========================================================================
#define LDH 136
#define PROJ_SMEM (4 * 128 * LDH * 2)

__device__ __forceinline__ void load_w_t(const float* __restrict__ W,
                                         __half* __restrict__ ws, int tid) {
#pragma unroll
    for (int j = 0; j < 16; j++) {
        int i  = tid + j * 256;        // 0..4095 quads
        int n  = i & 127;
        int kq = i >> 7;               // 0..31
        float w0 = W[(kq * 4 + 0) * HH + n];
        float w1 = W[(kq * 4 + 1) * HH + n];
        float w2 = W[(kq * 4 + 2) * HH + n];
        float w3 = W[(kq * 4 + 3) * HH + n];
        uint2 p = {h2bits(w0, w1), h2bits(w2, w3)};
        *(uint2*)&ws[n * LDH + kq * 4] = p;
    }
}

__global__ void __launch_bounds__(256, 1)
proj_mma(const float* __restrict__ x,
         const float* __restrict__ Wk,
         const float* __restrict__ Wq,
         const float* __restrict__ Wv,
         float* __restrict__ kout,
         float* __restrict__ vout)
{
    extern __shared__ __half smh[];
    __half* xs  = smh;
    __half* ws0 = smh + 128 * LDH;
    __half* ws1 = ws0 + 128 * LDH;
    __half* ws2 = ws1 + 128 * LDH;
    __half* vstage = ws1;              // reused after compute: [128 h][LDH t]

    const int tid  = threadIdx.x;
    const int tile = blockIdx.x;
    const int w    = tid >> 5;
    const int lane = tid & 31;
    const int g    = lane >> 2;
    const int c    = lane & 3;
    const int mbase = (w >> 1) * 32;
    const int nbase = (w & 1) * 64;

    // x tile -> xs (fp16, row-major)
    {
        const float4* xg = (const float4*)(x + (size_t)tile * 128 * CC);
#pragma unroll
        for (int j = 0; j < 16; j++) {
            int i4 = tid + j * 256;
            float4 v = xg[i4];
            int row = i4 >> 5;
            int c4  = (i4 & 31) * 4;
            uint2 p = {h2bits(v.x, v.y), h2bits(v.z, v.w)};
            *(uint2*)&xs[row * LDH + c4] = p;
        }
    }
    load_w_t(Wk, ws0, tid);
    load_w_t(Wq, ws1, tid);
    load_w_t(Wv, ws2, tid);
    __syncthreads();

    // ---- fused K+Q mma (8 k-steps of k16) ----
    float ak[2][8][4], aq[2][8][4];
#pragma unroll
    for (int mt = 0; mt < 2; mt++)
#pragma unroll
        for (int nt = 0; nt < 8; nt++)
#pragma unroll
            for (int e = 0; e < 4; e++) { ak[mt][nt][e] = 0.0f; aq[mt][nt][e] = 0.0f; }

#pragma unroll
    for (int kk = 0; kk < 8; kk++) {
        uint32_t a[2][4];
#pragma unroll
        for (int mt = 0; mt < 2; mt++) {
            const __half* xr = xs + (mbase + mt * 16 + g) * LDH + kk * 16 + 2 * c;
            a[mt][0] = *(const uint32_t*)(xr);
            a[mt][1] = *(const uint32_t*)(xr + 8 * LDH);
            a[mt][2] = *(const uint32_t*)(xr + 8);
            a[mt][3] = *(const uint32_t*)(xr + 8 * LDH + 8);
        }
#pragma unroll
        for (int nt = 0; nt < 8; nt++) {
            const __half* w0p = ws0 + (nbase + nt * 8 + g) * LDH + kk * 16 + 2 * c;
            const __half* w1p = ws1 + (nbase + nt * 8 + g) * LDH + kk * 16 + 2 * c;
            uint32_t bk0 = *(const uint32_t*)(w0p), bk1 = *(const uint32_t*)(w0p + 8);
            uint32_t bq0 = *(const uint32_t*)(w1p), bq1 = *(const uint32_t*)(w1p + 8);
            mma_f16(ak[0][nt], a[0], bk0, bk1);
            mma_f16(ak[1][nt], a[1], bk0, bk1);
            mma_f16(aq[0][nt], a[0], bq0, bq1);
            mma_f16(aq[1][nt], a[1], bq0, bq1);
        }
    }

    // K epilogue (fp32 + fp16) and Q epilogue (fp16 scaled)
#pragma unroll
    for (int mt = 0; mt < 2; mt++) {
#pragma unroll
        for (int nt = 0; nt < 8; nt++) {
            int row = tile * 128 + mbase + mt * 16 + g;
            int col = nbase + nt * 8 + 2 * c;
            const float* kk4 = ak[mt][nt];
            *(float2*)(kout + (size_t)row * HH + col)       = make_float2(kk4[0], kk4[1]);
            *(float2*)(kout + (size_t)(row + 8) * HH + col) = make_float2(kk4[2], kk4[3]);
            *(uint32_t*)&g_kh[(size_t)row * HH + col]       = h2bits(kk4[0], kk4[1]);
            *(uint32_t*)&g_kh[(size_t)(row + 8) * HH + col] = h2bits(kk4[2], kk4[3]);
            const float* q4 = aq[mt][nt];
            *(uint32_t*)&g_qh[(size_t)row * HH + col]       = h2bits(q4[0] * QSCALE, q4[1] * QSCALE);
            *(uint32_t*)&g_qh[(size_t)(row + 8) * HH + col] = h2bits(q4[2] * QSCALE, q4[3] * QSCALE);
        }
    }

    // ---- V phase (ws2 resident since prologue; xs unchanged) ----
    float av[2][8][4];
#pragma unroll
    for (int mt = 0; mt < 2; mt++)
#pragma unroll
        for (int nt = 0; nt < 8; nt++)
#pragma unroll
            for (int e = 0; e < 4; e++) av[mt][nt][e] = 0.0f;

#pragma unroll
    for (int kk = 0; kk < 8; kk++) {
        uint32_t a[2][4];
#pragma unroll
        for (int mt = 0; mt < 2; mt++) {
            const __half* xr = xs + (mbase + mt * 16 + g) * LDH + kk * 16 + 2 * c;
            a[mt][0] = *(const uint32_t*)(xr);
            a[mt][1] = *(const uint32_t*)(xr + 8 * LDH);
            a[mt][2] = *(const uint32_t*)(xr + 8);
            a[mt][3] = *(const uint32_t*)(xr + 8 * LDH + 8);
        }
#pragma unroll
        for (int nt = 0; nt < 8; nt++) {
            const __half* wp = ws2 + (nbase + nt * 8 + g) * LDH + kk * 16 + 2 * c;
            uint32_t b0 = *(const uint32_t*)(wp), b1 = *(const uint32_t*)(wp + 8);
            mma_f16(av[0][nt], a[0], b0, b1);
            mma_f16(av[1][nt], a[1], b0, b1);
        }
    }

    // V fp32 epilogue (coalesced)
#pragma unroll
    for (int mt = 0; mt < 2; mt++) {
#pragma unroll
        for (int nt = 0; nt < 8; nt++) {
            int row = tile * 128 + mbase + mt * 16 + g;
            int col = nbase + nt * 8 + 2 * c;
            const float* v4 = av[mt][nt];
            *(float2*)(vout + (size_t)row * HH + col)       = make_float2(v4[0], v4[1]);
            *(float2*)(vout + (size_t)(row + 8) * HH + col) = make_float2(v4[2], v4[3]);
        }
    }

    // ---- v fp16 transpose: stage [h][t] in smem, then coalesced STG ----
    __syncthreads();   // everyone done reading ws1/ws2 -> safe to reuse
#pragma unroll
    for (int mt = 0; mt < 2; mt++) {
#pragma unroll
        for (int nt = 0; nt < 8; nt++) {
            int rloc = mbase + mt * 16 + g;
            int col  = nbase + nt * 8 + 2 * c;
            const float* v4 = av[mt][nt];
            vstage[(col    ) * LDH + rloc]     = __float2half_rn(v4[0]);
            vstage[(col + 1) * LDH + rloc]     = __float2half_rn(v4[1]);
            vstage[(col    ) * LDH + rloc + 8] = __float2half_rn(v4[2]);
            vstage[(col + 1) * LDH + rloc + 8] = __float2half_rn(v4[3]);
        }
    }
    __syncthreads();
    {
        const size_t vb  = (size_t)(tile >> 1) * 128 * 256;   // batch base
        const int    ltb = (tile & 1) * 128;                  // token base
        int h    = tid & 127;
        int part = tid >> 7;          // 0/1: low/high 64 tokens of this tile
#pragma unroll
        for (int j = 0; j < 8; j++) {
            // 16B chunks: 8 halves per iteration (uint4), 8*8 = 64 tokens/part
            uint4 d = *(const uint4*)&vstage[h * LDH + part * 64 + j * 8];
            *(uint4*)&g_vt[vb + (size_t)h * 256 + ltb + part * 64 + j * 8] = d;
        }
    }
}

// ===========================================================================
// Kernel 2: causal flash attention (unchanged from R5).
// ===========================================================================
#define LKH 136
#define LVH 72
#define LPH 72
#define KBUF (64 * LKH)
#define VBUF (128 * LVH)
#define ATTN_SMEM ((2 * KBUF + 2 * VBUF + 128 * LPH) * 2)
#define NEG_BIG (-1.0e30f)

__global__ void __launch_bounds__(256, 1)
attn_mma(float* __restrict__ outg)
{
    extern __shared__ __half smh[];
    __half* Ks = smh;                 // [2][64][136]
    __half* Vt = Ks + 2 * KBUF;       // [2][128][72]
    __half* Ps = Vt + 2 * VBUF;       // [128][72]

    const int tid  = threadIdx.x;
    const int qt   = blockIdx.x;      // 0..1
    const int b    = blockIdx.y;      // 0..511
    const int w    = tid >> 5;
    const int lane = tid & 31;
    const int g    = lane >> 2;
    const int c    = lane & 3;
    const int rb   = w * 16;

    const uint32_t ks_a = smem_u32(Ks);
    const uint32_t vt_a = smem_u32(Vt);

    const __half* kh = g_kh + (size_t)b * TT * HH;      // [t][h]
    const __half* vt = g_vt + (size_t)b * 128 * 256;    // [h][t]
    const int nkt = qt ? 4 : 2;

    auto cp_stage = [&](int st) {
        uint32_t kd = ks_a + (uint32_t)((st & 1) * KBUF) * 2u;
        uint32_t vd = vt_a + (uint32_t)((st & 1) * VBUF) * 2u;
#pragma unroll
        for (int j = 0; j < 4; j++) {
            int i4 = tid + j * 256;
            int kr = i4 >> 4, kc = i4 & 15;
            cp_async16(kd + (uint32_t)(kr * LKH + kc * 8) * 2u,
                       kh + (size_t)(st * 64 + kr) * HH + kc * 8);
            int vr = i4 >> 3, vc = i4 & 7;
            cp_async16(vd + (uint32_t)(vr * LVH + vc * 8) * 2u,
                       vt + (size_t)vr * 256 + st * 64 + vc * 8);
        }
        CP_COMMIT();
    };

    cp_stage(0);

    // Q fragments -> registers
    uint32_t aq[8][4];
    {
        const __half* q0 = g_qh + ((size_t)b * TT + qt * 128 + rb + g) * HH + 2 * c;
        const __half* q1 = q0 + 8 * HH;
#pragma unroll
        for (int kk = 0; kk < 8; kk++) {
            aq[kk][0] = *(const uint32_t*)(q0 + kk * 16);
            aq[kk][1] = *(const uint32_t*)(q1 + kk * 16);
            aq[kk][2] = *(const uint32_t*)(q0 + kk * 16 + 8);
            aq[kk][3] = *(const uint32_t*)(q1 + kk * 16 + 8);
        }
    }

    float m0 = NEG_BIG, m1 = NEG_BIG, l0 = 0.0f, l1 = 0.0f;
    float o[16][4];
#pragma unroll
    for (int nt = 0; nt < 16; nt++)
#pragma unroll
        for (int e = 0; e < 4; e++) o[nt][e] = 0.0f;

    const int row0 = qt * 128 + rb + g;
    const int row1 = row0 + 8;

    for (int st = 0; st < nkt; st++) {
        CP_WAIT0();
        __syncthreads();
        if (st + 1 < nkt) cp_stage(st + 1);

        const __half* Kb = Ks + (st & 1) * KBUF;
        const __half* Vb = Vt + (st & 1) * VBUF;

        // S = Q K^T
        float s[8][4];
#pragma unroll
        for (int nt = 0; nt < 8; nt++)
#pragma unroll
            for (int e = 0; e < 4; e++) s[nt][e] = 0.0f;

#pragma unroll
        for (int kk = 0; kk < 8; kk++) {
#pragma unroll
            for (int nt = 0; nt < 8; nt++) {
                const __half* kr = Kb + (nt * 8 + g) * LKH + kk * 16 + 2 * c;
                uint32_t b0 = *(const uint32_t*)(kr);
                uint32_t b1 = *(const uint32_t*)(kr + 8);
                mma_f16(s[nt], aq[kk], b0, b1);
            }
        }

        // causal mask + online softmax (base 2, Q pre-scaled)
        float mx0 = NEG_BIG, mx1 = NEG_BIG;
#pragma unroll
        for (int nt = 0; nt < 8; nt++) {
            int k0 = st * 64 + nt * 8 + 2 * c;
            s[nt][0] = (k0     <= row0) ? s[nt][0] : NEG_BIG;
            s[nt][1] = (k0 + 1 <= row0) ? s[nt][1] : NEG_BIG;
            s[nt][2] = (k0     <= row1) ? s[nt][2] : NEG_BIG;
            s[nt][3] = (k0 + 1 <= row1) ? s[nt][3] : NEG_BIG;
            mx0 = fmaxf(mx0, fmaxf(s[nt][0], s[nt][1]));
            mx1 = fmaxf(mx1, fmaxf(s[nt][2], s[nt][3]));
        }
#pragma unroll
        for (int off = 1; off < 4; off <<= 1) {
            mx0 = fmaxf(mx0, __shfl_xor_sync(0xffffffffu, mx0, off));
            mx1 = fmaxf(mx1, __shfl_xor_sync(0xffffffffu, mx1, off));
        }
        float mn0 = fmaxf(m0, mx0);
        float mn1 = fmaxf(m1, mx1);
        float al0 = exp2f(m0 - mn0);
        float al1 = exp2f(m1 - mn1);
        float ps0 = 0.0f, ps1 = 0.0f;
#pragma unroll
        for (int nt = 0; nt < 8; nt++) {
            s[nt][0] = exp2f(s[nt][0] - mn0);
            s[nt][1] = exp2f(s[nt][1] - mn0);
            s[nt][2] = exp2f(s[nt][2] - mn1);
            s[nt][3] = exp2f(s[nt][3] - mn1);
            ps0 += s[nt][0] + s[nt][1];
            ps1 += s[nt][2] + s[nt][3];
        }
#pragma unroll
        for (int off = 1; off < 4; off <<= 1) {
            ps0 += __shfl_xor_sync(0xffffffffu, ps0, off);
            ps1 += __shfl_xor_sync(0xffffffffu, ps1, off);
        }
        l0 = l0 * al0 + ps0;
        l1 = l1 * al1 + ps1;
        m0 = mn0;
        m1 = mn1;
#pragma unroll
        for (int nt = 0; nt < 16; nt++) {
            o[nt][0] *= al0;
            o[nt][1] *= al0;
            o[nt][2] *= al1;
            o[nt][3] *= al1;
        }

        // stage P (fp16)
#pragma unroll
        for (int nt = 0; nt < 8; nt++) {
            *(uint32_t*)&Ps[(rb + g) * LPH + nt * 8 + 2 * c]     = h2bits(s[nt][0], s[nt][1]);
            *(uint32_t*)&Ps[(rb + g + 8) * LPH + nt * 8 + 2 * c] = h2bits(s[nt][2], s[nt][3]);
        }
        __syncwarp();

        // O += P @ V
#pragma unroll
        for (int kk = 0; kk < 4; kk++) {
            uint32_t a[4];
            const __half* pr = Ps + (rb + g) * LPH + kk * 16 + 2 * c;
            a[0] = *(const uint32_t*)(pr);
            a[1] = *(const uint32_t*)(pr + 8 * LPH);
            a[2] = *(const uint32_t*)(pr + 8);
            a[3] = *(const uint32_t*)(pr + 8 * LPH + 8);
#pragma unroll
            for (int nt = 0; nt < 16; nt++) {
                const __half* vr = Vb + (nt * 8 + g) * LVH + kk * 16 + 2 * c;
                uint32_t b0 = *(const uint32_t*)(vr);
                uint32_t b1 = *(const uint32_t*)(vr + 8);
                mma_f16(o[nt], a, b0, b1);
            }
        }
    }

    // normalize + write
    float inv0 = 1.0f / l0;
    float inv1 = 1.0f / l1;
    float* orow0 = outg + ((size_t)b * TT + qt * 128 + rb + g) * HH;
    float* orow1 = orow0 + 8 * HH;
#pragma unroll
    for (int nt = 0; nt < 16; nt++) {
        int col = nt * 8 + 2 * c;
        *(float2*)(orow0 + col) = make_float2(o[nt][0] * inv0, o[nt][1] * inv0);
        *(float2*)(orow1 + col) = make_float2(o[nt][2] * inv1, o[nt][3] * inv1);
    }
}

// ===========================================================================
extern "C" void kernel_launch(void* const* d_in, const int* in_sizes, int n_in,
                              void* d_out, int out_size)
{
    const float* x  = (const float*)d_in[0];
    const float* Wk = (const float*)d_in[1];
    const float* Wq = (const float*)d_in[2];
    const float* Wv = (const float*)d_in[3];

    float* out  = (float*)d_out;
    float* kout = out + (size_t)BTH;
    float* vout = out + 2 * (size_t)BTH;

    cudaFuncSetAttribute(proj_mma, cudaFuncAttributeMaxDynamicSharedMemorySize, PROJ_SMEM);
    cudaFuncSetAttribute(attn_mma, cudaFuncAttributeMaxDynamicSharedMemorySize, ATTN_SMEM);

    proj_mma<<<1024, 256, PROJ_SMEM>>>(x, Wk, Wq, Wv, kout, vout);
    attn_mma<<<dim3(2, 512), 256, ATTN_SMEM>>>(out);
}